// round 8
// baseline (speedup 1.0000x reference)
#include <cuda_runtime.h>
#include <cuda_bf16.h>
#include <math.h>
#include <stdint.h>

#define Bv 128
#define Tv 256
#define Hv 1024
#define GRID 128
#define NTHR 512

// ---------------- scratch -----------------------------------------------------
__device__ __nv_bfloat16 g_xh[(size_t)Bv * Tv * Hv];
__device__ __nv_bfloat16 g_xl[(size_t)Bv * Tv * Hv];
__device__ __nv_bfloat16 g_Wth[4][(size_t)Hv * Hv];   // [n][k] hi: 0:Wh0 1:Wi1 2:Wh1 3:Wi0
__device__ __nv_bfloat16 g_Wtl[4][(size_t)Hv * Hv];   // [n][k] lo
__device__ __nv_bfloat16 g_h0h[2][Bv * Hv], g_h0l[2][Bv * Hv];
__device__ __nv_bfloat16 g_h1h[2][Bv * Hv], g_h1l[2][Bv * Hv];
__device__ float g_bsum[2 * Hv];
__device__ float g_xb0[(size_t)Bv * Tv * Hv];         // x @ Wi0 (fp32), [b][t][h]
__device__ unsigned g_arrive, g_gen;

// ---------------- smem layouts ---------------------------------------------------
// k_persist buffer (44KB x2): A0h|A0l|A1h|A1l (8KB each) | W 6 tiles x 2KB
#define OFF_A0H(b) ((b) * 45056)
#define OFF_A0L(b) ((b) * 45056 + 8192)
#define OFF_A1H(b) ((b) * 45056 + 16384)
#define OFF_A1L(b) ((b) * 45056 + 24576)
#define OFF_W(b)   ((b) * 45056 + 32768)
#define SMEM_SZ    90112
// k_xb0 buffer (32KB x2): Ah|Al|Wh|Wl (8KB each)
#define XOFF_AH(b) ((b) * 32768)
#define XOFF_AL(b) ((b) * 32768 + 8192)
#define XOFF_WH(b) ((b) * 32768 + 16384)
#define XOFF_WL(b) ((b) * 32768 + 24576)
#define SMEM_XB    65536

// ---------------- PTX helpers ---------------------------------------------------
__device__ __forceinline__ uint32_t smem_u32(const void* p) {
    uint32_t a;
    asm("{ .reg .u64 t; cvta.to.shared.u64 t, %1; cvt.u32.u64 %0, t; }" : "=r"(a) : "l"(p));
    return a;
}
__device__ __forceinline__ uint32_t swz(uint32_t o) { return o ^ ((o >> 3) & 0x70); }
__device__ __forceinline__ void cp16(uint32_t s, const void* g) {
    asm volatile("cp.async.cg.shared.global [%0], [%1], 16;" :: "r"(s), "l"(g));
}
__device__ __forceinline__ void ldm4(uint32_t* r, uint32_t addr) {
    asm volatile("ldmatrix.sync.aligned.m8n8.x4.shared.b16 {%0,%1,%2,%3}, [%4];"
        : "=r"(r[0]), "=r"(r[1]), "=r"(r[2]), "=r"(r[3]) : "r"(addr));
}
__device__ __forceinline__ void mma16816(float* c, const uint32_t* a, const uint32_t* b) {
    asm volatile("mma.sync.aligned.m16n8k16.row.col.f32.bf16.bf16.f32 "
        "{%0,%1,%2,%3}, {%4,%5,%6,%7}, {%8,%9}, {%0,%1,%2,%3};"
        : "+f"(c[0]), "+f"(c[1]), "+f"(c[2]), "+f"(c[3])
        : "r"(a[0]), "r"(a[1]), "r"(a[2]), "r"(a[3]), "r"(b[0]), "r"(b[1]));
}

// ---------------- grid barrier ----------------------------------------------------
__device__ __forceinline__ void gbar(unsigned expect) {
    __threadfence();
    __syncthreads();
    if (threadIdx.x == 0) {
        unsigned a = atomicAdd(&g_arrive, 1u);
        if (a == GRID - 1) {
            atomicExch(&g_arrive, 0u);
            __threadfence();
            atomicAdd(&g_gen, 1u);
        } else {
            while (*(volatile unsigned*)&g_gen < expect) { __nanosleep(64); }
        }
        __threadfence();
    }
    __syncthreads();
}

// ---------------- bf16 split helpers ------------------------------------------------
__device__ __forceinline__ void split4(float4 v, uint2& uh, uint2& ul) {
    __nv_bfloat16 h0 = __float2bfloat16_rn(v.x), h1 = __float2bfloat16_rn(v.y);
    __nv_bfloat16 h2 = __float2bfloat16_rn(v.z), h3 = __float2bfloat16_rn(v.w);
    __nv_bfloat16 l0 = __float2bfloat16_rn(v.x - __bfloat162float(h0));
    __nv_bfloat16 l1 = __float2bfloat16_rn(v.y - __bfloat162float(h1));
    __nv_bfloat16 l2 = __float2bfloat16_rn(v.z - __bfloat162float(h2));
    __nv_bfloat16 l3 = __float2bfloat16_rn(v.w - __bfloat162float(h3));
    uh.x = (uint32_t)__bfloat16_as_ushort(h0) | ((uint32_t)__bfloat16_as_ushort(h1) << 16);
    uh.y = (uint32_t)__bfloat16_as_ushort(h2) | ((uint32_t)__bfloat16_as_ushort(h3) << 16);
    ul.x = (uint32_t)__bfloat16_as_ushort(l0) | ((uint32_t)__bfloat16_as_ushort(l1) << 16);
    ul.y = (uint32_t)__bfloat16_as_ushort(l2) | ((uint32_t)__bfloat16_as_ushort(l3) << 16);
}
__device__ __forceinline__ void split2(float a, float b, uint32_t& uh, uint32_t& ul) {
    __nv_bfloat16 h0 = __float2bfloat16_rn(a), h1 = __float2bfloat16_rn(b);
    __nv_bfloat16 l0 = __float2bfloat16_rn(a - __bfloat162float(h0));
    __nv_bfloat16 l1 = __float2bfloat16_rn(b - __bfloat162float(h1));
    uh = (uint32_t)__bfloat16_as_ushort(h0) | ((uint32_t)__bfloat16_as_ushort(h1) << 16);
    ul = (uint32_t)__bfloat16_as_ushort(l0) | ((uint32_t)__bfloat16_as_ushort(l1) << 16);
}

// ---------------- prep kernels -------------------------------------------------------
__global__ void __launch_bounds__(256) k_init(const float* __restrict__ h0in,
                                              const float* __restrict__ bi,
                                              const float* __restrict__ bh)
{
    int idx = blockIdx.x * 256 + threadIdx.x;
    if (idx == 0) { g_arrive = 0u; g_gen = 0u; }
    if (idx < 2 * Hv) g_bsum[idx] = bi[idx] + bh[idx];
    int j = idx & (Hv - 1);
    float v0 = h0in[j], v1 = h0in[Hv + j];
    __nv_bfloat16 h = __float2bfloat16_rn(v0);
    __nv_bfloat16 l = __float2bfloat16_rn(v0 - __bfloat162float(h));
    g_h0h[0][idx] = h; g_h0l[0][idx] = l; g_h0h[1][idx] = h; g_h0l[1][idx] = l;
    h = __float2bfloat16_rn(v1);
    l = __float2bfloat16_rn(v1 - __bfloat162float(h));
    g_h1h[0][idx] = h; g_h1l[0][idx] = l; g_h1h[1][idx] = h; g_h1l[1][idx] = l;
}

__global__ void __launch_bounds__(256) k_splitx(const float* __restrict__ x)
{
    size_t i = (size_t)blockIdx.x * 256 + threadIdx.x;
    float4 v = ((const float4*)x)[i];
    uint2 uh, ul;
    split4(v, uh, ul);
    ((uint2*)g_xh)[i] = uh;
    ((uint2*)g_xl)[i] = ul;
}

__global__ void k_splitw(const float* __restrict__ Wi, const float* __restrict__ Wh)
{
    __shared__ float t[32][33];
    int m = blockIdx.z;
    const float* W = (m == 0) ? Wh
                   : (m == 1) ? (Wi + (size_t)Hv * Hv)
                   : (m == 2) ? (Wh + (size_t)Hv * Hv) : Wi;
    int k0 = blockIdx.y * 32, n0 = blockIdx.x * 32;
    for (int r = threadIdx.y; r < 32; r += 8)
        t[r][threadIdx.x] = W[(size_t)(k0 + r) * Hv + n0 + threadIdx.x];
    __syncthreads();
    for (int r = threadIdx.y; r < 32; r += 8) {
        float v = t[threadIdx.x][r];
        __nv_bfloat16 h = __float2bfloat16_rn(v);
        __nv_bfloat16 l = __float2bfloat16_rn(v - __bfloat162float(h));
        size_t o = (size_t)(n0 + r) * Hv + k0 + threadIdx.x;
        g_Wth[m][o] = h;
        g_Wtl[m][o] = l;
    }
}

// ---------------- xb0 = x @ Wi0 (bf16x3, fp32 out) -----------------------------------
// grid (512, 16); CTA tile 64x64; 16 warps = 4 m-slices x 4 k-quarters
__global__ void __launch_bounds__(NTHR) k_xb0()
{
    extern __shared__ char smem[];
    const uint32_t sb = smem_u32(smem);
    const int tid = threadIdx.x, lane = tid & 31, wid = tid >> 5;
    const int mslice = wid & 3, kq = wid >> 2;
    const int mt = blockIdx.x, nt = blockIdx.y;

    const int mA = mslice * 16 + ((lane >> 3) & 1) * 8 + (lane & 7);
    const uint32_t abase = (uint32_t)(mA * 128);
    const uint32_t ka = ((uint32_t)(kq * 32 + ((lane >> 4) & 1) * 16)) ^ (uint32_t)((mA & 7) * 16);
    const int nW = ((lane >> 4) & 1) * 8 + (lane & 7);
    const uint32_t wbase = (uint32_t)(nW * 128);
    const uint32_t kw = ((uint32_t)(kq * 32 + ((lane >> 3) & 1) * 16)) ^ (uint32_t)((nW & 7) * 16);

    const __nv_bfloat16* Ah = g_xh + (size_t)(mt * 64) * Hv;
    const __nv_bfloat16* Al = g_xl + (size_t)(mt * 64) * Hv;
    const __nv_bfloat16* Wh_ = g_Wth[3] + (size_t)(nt * 64) * Hv;
    const __nv_bfloat16* Wl_ = g_Wtl[3] + (size_t)(nt * 64) * Hv;

    auto load_chunk = [&](int b, int c) {
        int row = tid >> 3, kg = tid & 7;
        uint32_t so = swz(row * 128 + kg * 16);
        size_t go = (size_t)row * Hv + c * 64 + kg * 8;
        cp16(sb + XOFF_AH(b) + so, Ah + go);
        cp16(sb + XOFF_AL(b) + so, Al + go);
        cp16(sb + XOFF_WH(b) + so, Wh_ + go);
        cp16(sb + XOFF_WL(b) + so, Wl_ + go);
        asm volatile("cp.async.commit_group;" ::: "memory");
    };

    float acc[8][4];
#pragma unroll
    for (int i = 0; i < 8; i++)
#pragma unroll
        for (int q = 0; q < 4; q++) acc[i][q] = 0.f;

    load_chunk(0, 0);
    load_chunk(1, 1);

#pragma unroll 1
    for (int c = 0; c < 16; c++) {
        const int b = c & 1;
        if (c < 15) asm volatile("cp.async.wait_group 1;" ::: "memory");
        else        asm volatile("cp.async.wait_group 0;" ::: "memory");
        __syncthreads();
        uint32_t ah[4], al_[4];
        ldm4(ah,  sb + XOFF_AH(b) + abase + ka);
        ldm4(al_, sb + XOFF_AL(b) + abase + ka);
#pragma unroll
        for (int ng = 0; ng < 4; ng++) {
            uint32_t wh[4], wl[4];
            ldm4(wh, sb + XOFF_WH(b) + ng * 2048 + wbase + kw);
            ldm4(wl, sb + XOFF_WL(b) + ng * 2048 + wbase + kw);
#pragma unroll
            for (int jj = 0; jj < 2; jj++) {
                float* a_ = acc[ng * 2 + jj];
                mma16816(a_, ah,  &wh[jj * 2]);
                mma16816(a_, al_, &wh[jj * 2]);
                mma16816(a_, ah,  &wl[jj * 2]);
            }
        }
        __syncthreads();
        if (c + 2 < 16) load_chunk(b, c + 2);
    }

    // combine k-quarters via smem
    float* cmb = (float*)smem;
    if (kq) {
        int wix = (kq - 1) * 4 + mslice;
#pragma unroll
        for (int r = 0; r < 32; r++)
            cmb[wix * 1024 + r * 32 + lane] = acc[r >> 2][r & 3];
    }
    __syncthreads();
    if (!kq) {
        const int g = lane >> 2, t2 = (lane & 3) * 2;
#pragma unroll
        for (int t = 0; t < 8; t++) {
#pragma unroll
            for (int hq = 0; hq < 2; hq++) {
                int r0 = t * 4 + hq * 2, r1 = r0 + 1;
                float v0 = acc[t][hq * 2 + 0], v1 = acc[t][hq * 2 + 1];
#pragma unroll
                for (int kk = 0; kk < 3; kk++) {
                    v0 += cmb[(kk * 4 + mslice) * 1024 + r0 * 32 + lane];
                    v1 += cmb[(kk * 4 + mslice) * 1024 + r1 * 32 + lane];
                }
                int Mr = mt * 64 + mslice * 16 + g + hq * 8;
                int col = nt * 64 + t * 8 + t2;
                float2 o; o.x = v0; o.y = v1;
                *(float2*)&g_xb0[(size_t)Mr * Hv + col] = o;
            }
        }
    }
}

// ---------------- persistent wavefront kernel -----------------------------------------
// 128 CTAs: rh = blk>>6 (64-row half), cg = blk&63 (16-col group).
// OUT0 (64x16) = h0@Wh0 [+xb0,+b0,tanh -> new h0];  OUT1 (64x16) = h0@Wi1 + h1@Wh1 [+b1,tanh -> new h1, out]
__global__ void __launch_bounds__(NTHR)
k_persist(float* __restrict__ out, int has_hn)
{
    extern __shared__ char smem[];
    const uint32_t sb = smem_u32(smem);
    const int tid = threadIdx.x, lane = tid & 31, wid = tid >> 5;
    const int mslice = wid & 3, kq = wid >> 2;
    const int rh = blockIdx.x >> 6, cg = blockIdx.x & 63;

    const int mA = mslice * 16 + ((lane >> 3) & 1) * 8 + (lane & 7);
    const uint32_t abase = (uint32_t)(mA * 128);
    const uint32_t ka = ((uint32_t)(kq * 32 + ((lane >> 4) & 1) * 16)) ^ (uint32_t)((mA & 7) * 16);
    const int nW = ((lane >> 4) & 1) * 8 + (lane & 7);
    const uint32_t wbase = (uint32_t)(nW * 128);
    const uint32_t kw = ((uint32_t)(kq * 32 + ((lane >> 3) & 1) * 16)) ^ (uint32_t)((nW & 7) * 16);

    __shared__ const __nv_bfloat16* Wp[6];
    if (tid < 3) {
        Wp[tid * 2]     = g_Wth[tid] + (size_t)(cg * 16) * Hv;
        Wp[tid * 2 + 1] = g_Wtl[tid] + (size_t)(cg * 16) * Hv;
    }
    __syncthreads();

    unsigned expect = 0;

    for (int w = 0; w <= Tv; w++) {
        const int p = w & 1;
        const __nv_bfloat16* A0h = g_h0h[p] + (size_t)rh * 64 * Hv;
        const __nv_bfloat16* A0l = g_h0l[p] + (size_t)rh * 64 * Hv;
        const __nv_bfloat16* A1h = g_h1h[p] + (size_t)rh * 64 * Hv;
        const __nv_bfloat16* A1l = g_h1l[p] + (size_t)rh * 64 * Hv;

        auto load_chunk = [&](int b, int c) {
            {
                int row = tid >> 3, kg = tid & 7;
                uint32_t so = swz(row * 128 + kg * 16);
                size_t go = (size_t)row * Hv + c * 64 + kg * 8;
                cp16(sb + OFF_A0H(b) + so, A0h + go);
                cp16(sb + OFF_A0L(b) + so, A0l + go);
                cp16(sb + OFF_A1H(b) + so, A1h + go);
                cp16(sb + OFF_A1L(b) + so, A1l + go);
            }
#pragma unroll
            for (int r = 0; r < 2; r++) {
                int i = tid + r * 512;
                if (i < 768) {
                    int t = i >> 7, row = (i >> 3) & 15, kg = i & 7;
                    cp16(sb + OFF_W(b) + t * 2048 + swz(row * 128 + kg * 16),
                         Wp[t] + (size_t)row * Hv + c * 64 + kg * 8);
                }
            }
            asm volatile("cp.async.commit_group;" ::: "memory");
        };

        float acc0[2][4], acc1[2][4];
#pragma unroll
        for (int j = 0; j < 2; j++)
#pragma unroll
            for (int q = 0; q < 4; q++) { acc0[j][q] = 0.f; acc1[j][q] = 0.f; }

        load_chunk(0, 0);
        load_chunk(1, 1);

#pragma unroll 1
        for (int c = 0; c < 16; c++) {
            const int b = c & 1;
            if (c < 15) asm volatile("cp.async.wait_group 1;" ::: "memory");
            else        asm volatile("cp.async.wait_group 0;" ::: "memory");
            __syncthreads();

            uint32_t a0h[4], a0l[4], a1h[4], a1l[4];
            uint32_t w0h[4], w0l[4], w1h[4], w1l[4], w2h[4], w2l[4];
            ldm4(a0h, sb + OFF_A0H(b) + abase + ka);
            ldm4(a0l, sb + OFF_A0L(b) + abase + ka);
            ldm4(a1h, sb + OFF_A1H(b) + abase + ka);
            ldm4(a1l, sb + OFF_A1L(b) + abase + ka);
            uint32_t wb = sb + OFF_W(b) + wbase + kw;
            ldm4(w0h, wb);          ldm4(w0l, wb + 2048);
            ldm4(w1h, wb + 4096);   ldm4(w1l, wb + 6144);
            ldm4(w2h, wb + 8192);   ldm4(w2l, wb + 10240);
#pragma unroll
            for (int j = 0; j < 2; j++) {
                mma16816(acc0[j], a0h, &w0h[j * 2]);
                mma16816(acc0[j], a0l, &w0h[j * 2]);
                mma16816(acc0[j], a0h, &w0l[j * 2]);
                mma16816(acc1[j], a0h, &w1h[j * 2]);
                mma16816(acc1[j], a0l, &w1h[j * 2]);
                mma16816(acc1[j], a0h, &w1l[j * 2]);
                mma16816(acc1[j], a1h, &w2h[j * 2]);
                mma16816(acc1[j], a1l, &w2h[j * 2]);
                mma16816(acc1[j], a1h, &w2l[j * 2]);
            }
            __syncthreads();
            if (c + 2 < 16) load_chunk(b, c + 2);
        }

        // combine k-quarters
        float* cmb = (float*)smem;
        if (kq) {
            int wix = (kq - 1) * 4 + mslice;
#pragma unroll
            for (int r = 0; r < 8; r++) {
                cmb[wix * 512 + r * 32 + lane]        = acc0[r >> 2][r & 3];
                cmb[wix * 512 + (r + 8) * 32 + lane]  = acc1[r >> 2][r & 3];
            }
        }
        __syncthreads();
        if (!kq) {
#pragma unroll
            for (int r = 0; r < 8; r++) {
#pragma unroll
                for (int kk = 0; kk < 3; kk++) {
                    acc0[r >> 2][r & 3] += cmb[(kk * 4 + mslice) * 512 + r * 32 + lane];
                    acc1[r >> 2][r & 3] += cmb[(kk * 4 + mslice) * 512 + (r + 8) * 32 + lane];
                }
            }
            const int g = lane >> 2, t2 = (lane & 3) * 2;
#pragma unroll
            for (int j = 0; j < 2; j++) {
                int cl = cg * 16 + j * 8 + t2;
                float2 bs0 = *(float2*)&g_bsum[cl];
                float2 bs1 = *(float2*)&g_bsum[Hv + cl];
#pragma unroll
                for (int hq = 0; hq < 2; hq++) {
                    int b = rh * 64 + mslice * 16 + g + hq * 8;
                    if (w < Tv) {
                        float2 xb = *(float2*)&g_xb0[((size_t)b * Tv + w) * Hv + cl];
                        float z0 = tanhf(acc0[j][hq * 2 + 0] + xb.x + bs0.x);
                        float z1 = tanhf(acc0[j][hq * 2 + 1] + xb.y + bs0.y);
                        uint32_t uh, ul;
                        split2(z0, z1, uh, ul);
                        *(uint32_t*)&g_h0h[p ^ 1][b * Hv + cl] = uh;
                        *(uint32_t*)&g_h0l[p ^ 1][b * Hv + cl] = ul;
                        if (w == Tv - 1 && has_hn) {
                            float2 o; o.x = z0; o.y = z1;
                            *(float2*)&out[(size_t)Bv * Tv * Hv + (size_t)b * 2 * Hv + cl] = o;
                        }
                    }
                    if (w >= 1) {
                        float z0 = tanhf(acc1[j][hq * 2 + 0] + bs1.x);
                        float z1 = tanhf(acc1[j][hq * 2 + 1] + bs1.y);
                        uint32_t uh, ul;
                        split2(z0, z1, uh, ul);
                        *(uint32_t*)&g_h1h[p ^ 1][b * Hv + cl] = uh;
                        *(uint32_t*)&g_h1l[p ^ 1][b * Hv + cl] = ul;
                        float2 o; o.x = z0; o.y = z1;
                        *(float2*)&out[((size_t)b * Tv + (w - 1)) * Hv + cl] = o;
                        if (w == Tv && has_hn)
                            *(float2*)&out[(size_t)Bv * Tv * Hv + (size_t)b * 2 * Hv + Hv + cl] = o;
                    }
                }
            }
        }
        gbar(++expect);
    }
}

// ---------------- launcher -----------------------------------------------------------
extern "C" void kernel_launch(void* const* d_in, const int* in_sizes, int n_in,
                              void* d_out, int out_size)
{
    (void)in_sizes; (void)n_in;
    const float* x  = (const float*)d_in[0];
    const float* h0 = (const float*)d_in[1];
    const float* Wi = (const float*)d_in[2];
    const float* bi = (const float*)d_in[3];
    const float* Wh = (const float*)d_in[4];
    const float* bh = (const float*)d_in[5];
    float* out = (float*)d_out;

    cudaFuncSetAttribute(k_persist, cudaFuncAttributeMaxDynamicSharedMemorySize, SMEM_SZ);
    cudaFuncSetAttribute(k_xb0, cudaFuncAttributeMaxDynamicSharedMemorySize, SMEM_XB);

    int has_hn = (out_size >= Bv * Tv * Hv + Bv * 2 * Hv) ? 1 : 0;

    k_init<<<512, 256>>>(h0, bi, bh);
    k_splitx<<<32768, 256>>>(x);
    k_splitw<<<dim3(32, 32, 4), dim3(32, 8)>>>(Wi, Wh);
    k_xb0<<<dim3(512, 16), NTHR, SMEM_XB>>>();
    k_persist<<<GRID, NTHR, SMEM_SZ>>>(out, has_hn);
}

// round 9
// speedup vs baseline: 1.6133x; 1.6133x over previous
#include <cuda_runtime.h>
#include <cuda_bf16.h>
#include <math.h>
#include <stdint.h>

#define Bv 128
#define Tv 256
#define Hv 1024
#define GRID 128
#define NTHR 512

// ---------------- scratch -----------------------------------------------------
__device__ __nv_bfloat16 g_xh[(size_t)Bv * Tv * Hv];
__device__ __nv_bfloat16 g_xl[(size_t)Bv * Tv * Hv];
__device__ __nv_bfloat16 g_Wth[4][(size_t)Hv * Hv];   // [n][k] hi: 0:Wh0 1:Wi1 2:Wh1 3:Wi0
__device__ __nv_bfloat16 g_Wtl[4][(size_t)Hv * Hv];   // [n][k] lo
__device__ __nv_bfloat16 g_h0h[2][Bv * Hv], g_h0l[2][Bv * Hv];
__device__ __nv_bfloat16 g_h1h[2][Bv * Hv], g_h1l[2][Bv * Hv];
__device__ float g_bsum[2 * Hv];
__device__ float g_C[(size_t)Bv * 4096];
__device__ unsigned g_arrive, g_gen;

// ---------------- smem layout (dynamic) -----------------------------------------
// [0, 128K)   resident Wh slice: 16 chunk-tiles of 8KB
// [128K, ..)  double-buffered stream chunks: Ah | Al | Wl (8KB each)
// epilogue combine area (48KB) overlays the whole stream area (dead then)
#define OFF_WRES  0
#define OFF_AH(b) (131072 + (b) * 24576)
#define OFF_AL(b) (131072 + (b) * 24576 + 8192)
#define OFF_WL(b) (131072 + (b) * 24576 + 16384)
#define OFF_CMB   131072
#define SMEM_SZ   180224

// ---------------- PTX helpers ---------------------------------------------------
__device__ __forceinline__ uint32_t smem_u32(const void* p) {
    uint32_t a;
    asm("{ .reg .u64 t; cvta.to.shared.u64 t, %1; cvt.u32.u64 %0, t; }" : "=r"(a) : "l"(p));
    return a;
}
__device__ __forceinline__ uint32_t swz(uint32_t o) { return o ^ ((o >> 3) & 0x70); }
__device__ __forceinline__ void cp16(uint32_t s, const void* g) {
    asm volatile("cp.async.cg.shared.global [%0], [%1], 16;" :: "r"(s), "l"(g));
}
__device__ __forceinline__ void ldm4(uint32_t* r, uint32_t addr) {
    asm volatile("ldmatrix.sync.aligned.m8n8.x4.shared.b16 {%0,%1,%2,%3}, [%4];"
        : "=r"(r[0]), "=r"(r[1]), "=r"(r[2]), "=r"(r[3]) : "r"(addr));
}
__device__ __forceinline__ void mma16816(float* c, const uint32_t* a, const uint32_t* b) {
    asm volatile("mma.sync.aligned.m16n8k16.row.col.f32.bf16.bf16.f32 "
        "{%0,%1,%2,%3}, {%4,%5,%6,%7}, {%8,%9}, {%0,%1,%2,%3};"
        : "+f"(c[0]), "+f"(c[1]), "+f"(c[2]), "+f"(c[3])
        : "r"(a[0]), "r"(a[1]), "r"(a[2]), "r"(a[3]), "r"(b[0]), "r"(b[1]));
}

// ---------------- grid barrier ----------------------------------------------------
__device__ __forceinline__ void gbar(unsigned expect) {
    __threadfence();
    __syncthreads();
    if (threadIdx.x == 0) {
        unsigned a = atomicAdd(&g_arrive, 1u);
        if (a == GRID - 1) {
            atomicExch(&g_arrive, 0u);
            __threadfence();
            atomicAdd(&g_gen, 1u);
        } else {
            while (*(volatile unsigned*)&g_gen < expect) { __nanosleep(64); }
        }
        __threadfence();
    }
    __syncthreads();
}

// ---------------- bf16 split helpers ------------------------------------------------
__device__ __forceinline__ void split4(float4 v, uint2& uh, uint2& ul) {
    __nv_bfloat16 h0 = __float2bfloat16_rn(v.x), h1 = __float2bfloat16_rn(v.y);
    __nv_bfloat16 h2 = __float2bfloat16_rn(v.z), h3 = __float2bfloat16_rn(v.w);
    __nv_bfloat16 l0 = __float2bfloat16_rn(v.x - __bfloat162float(h0));
    __nv_bfloat16 l1 = __float2bfloat16_rn(v.y - __bfloat162float(h1));
    __nv_bfloat16 l2 = __float2bfloat16_rn(v.z - __bfloat162float(h2));
    __nv_bfloat16 l3 = __float2bfloat16_rn(v.w - __bfloat162float(h3));
    uh.x = (uint32_t)__bfloat16_as_ushort(h0) | ((uint32_t)__bfloat16_as_ushort(h1) << 16);
    uh.y = (uint32_t)__bfloat16_as_ushort(h2) | ((uint32_t)__bfloat16_as_ushort(h3) << 16);
    ul.x = (uint32_t)__bfloat16_as_ushort(l0) | ((uint32_t)__bfloat16_as_ushort(l1) << 16);
    ul.y = (uint32_t)__bfloat16_as_ushort(l2) | ((uint32_t)__bfloat16_as_ushort(l3) << 16);
}
__device__ __forceinline__ void split2(float a, float b, uint32_t& uh, uint32_t& ul) {
    __nv_bfloat16 h0 = __float2bfloat16_rn(a), h1 = __float2bfloat16_rn(b);
    __nv_bfloat16 l0 = __float2bfloat16_rn(a - __bfloat162float(h0));
    __nv_bfloat16 l1 = __float2bfloat16_rn(b - __bfloat162float(h1));
    uh = (uint32_t)__bfloat16_as_ushort(h0) | ((uint32_t)__bfloat16_as_ushort(h1) << 16);
    ul = (uint32_t)__bfloat16_as_ushort(l0) | ((uint32_t)__bfloat16_as_ushort(l1) << 16);
}

// ---------------- prep kernels -------------------------------------------------------
__global__ void __launch_bounds__(256) k_init(const float* __restrict__ h0in,
                                              const float* __restrict__ bi,
                                              const float* __restrict__ bh)
{
    int idx = blockIdx.x * 256 + threadIdx.x;
    if (idx == 0) { g_arrive = 0u; g_gen = 0u; }
    if (idx < 2 * Hv) g_bsum[idx] = bi[idx] + bh[idx];
    int j = idx & (Hv - 1);
    float v0 = h0in[j], v1 = h0in[Hv + j];
    __nv_bfloat16 h = __float2bfloat16_rn(v0);
    __nv_bfloat16 l = __float2bfloat16_rn(v0 - __bfloat162float(h));
    g_h0h[0][idx] = h; g_h0l[0][idx] = l; g_h0h[1][idx] = h; g_h0l[1][idx] = l;
    h = __float2bfloat16_rn(v1);
    l = __float2bfloat16_rn(v1 - __bfloat162float(h));
    g_h1h[0][idx] = h; g_h1l[0][idx] = l; g_h1h[1][idx] = h; g_h1l[1][idx] = l;
}

__global__ void __launch_bounds__(256) k_splitx(const float* __restrict__ x)
{
    size_t i = (size_t)blockIdx.x * 256 + threadIdx.x;
    float4 v = ((const float4*)x)[i];
    uint2 uh, ul;
    split4(v, uh, ul);
    ((uint2*)g_xh)[i] = uh;
    ((uint2*)g_xl)[i] = ul;
}

__global__ void k_splitw(const float* __restrict__ Wi, const float* __restrict__ Wh)
{
    __shared__ float t[32][33];
    int m = blockIdx.z;
    const float* W = (m == 0) ? Wh
                   : (m == 1) ? (Wi + (size_t)Hv * Hv)
                   : (m == 2) ? (Wh + (size_t)Hv * Hv) : Wi;
    int k0 = blockIdx.y * 32, n0 = blockIdx.x * 32;
    for (int r = threadIdx.y; r < 32; r += 8)
        t[r][threadIdx.x] = W[(size_t)(k0 + r) * Hv + n0 + threadIdx.x];
    __syncthreads();
    for (int r = threadIdx.y; r < 32; r += 8) {
        float v = t[threadIdx.x][r];
        __nv_bfloat16 h = __float2bfloat16_rn(v);
        __nv_bfloat16 l = __float2bfloat16_rn(v - __bfloat162float(h));
        size_t o = (size_t)(n0 + r) * Hv + k0 + threadIdx.x;
        g_Wth[m][o] = h;
        g_Wtl[m][o] = l;
    }
}

// ---------------- persistent wavefront kernel -----------------------------------------
// 128 CTAs: blockIdx = (col tile 0..63) * 2 + (row half 0..1). CTA tile C[64, 64].
// seg = coltile>>4: 0: h0@Wh0   1: h0@Wi1   2: h1@Wh1   3: x_t@Wi0
// 16 warps: tw = wid&3 -> (wr: m32 half, wc: n32 half); kq = wid>>2 does kstep kq
// of each k64 chunk. 4 k-partials combined in smem, kq0 warps write C.
__global__ void __launch_bounds__(NTHR)
k_persist(float* __restrict__ out, int has_hn)
{
    extern __shared__ char smem[];
    const uint32_t sb = smem_u32(smem);
    const int tid  = threadIdx.x;
    const int lane = tid & 31;
    const int wid  = tid >> 5;
    const int ctc  = blockIdx.x >> 1;
    const int r0   = (blockIdx.x & 1) * 64;
    const int seg  = ctc >> 4;
    const int nloc = (ctc & 15) * 64;

    const int tw = wid & 3, kq = wid >> 2;
    const int wr = tw & 1, wc = tw >> 1;

    // A fragment addressing (two m16 tiles at rows wr*32 and wr*32+16)
    const int mA    = wr * 32 + ((lane >> 3) & 1) * 8 + (lane & 7);
    const uint32_t xorA   = (uint32_t)((mA & 7) * 16);
    const uint32_t abase0 = (uint32_t)(mA * 128);
    const uint32_t abase1 = (uint32_t)((mA + 16) * 128);
    const uint32_t ka = ((uint32_t)(kq * 32 + ((lane >> 4) & 1) * 16)) ^ xorA;

    // W fragment addressing (two n16 groups)
    const int nW    = wc * 32 + ((lane >> 4) & 1) * 8 + (lane & 7);
    const uint32_t xorW   = (uint32_t)((nW & 7) * 16);
    const uint32_t wbase0 = (uint32_t)(nW * 128);
    const uint32_t wbase1 = wbase0 + 16 * 128;
    const uint32_t kw = ((uint32_t)(kq * 32 + ((lane >> 3) & 1) * 16)) ^ xorW;

    const __nv_bfloat16* Whb = g_Wth[seg] + (size_t)nloc * Hv;
    const __nv_bfloat16* Wlb = g_Wtl[seg] + (size_t)nloc * Hv;

    auto load_tile = [&](uint32_t dst, const __nv_bfloat16* src, size_t rs) {
        int row = tid >> 3, kg = tid & 7;
        cp16(dst + swz(row * 128 + kg * 16), src + (size_t)row * rs + kg * 8);
    };

    // ---- load resident Wh slice (once) ----
    for (int c = 0; c < 16; c++)
        load_tile(sb + OFF_WRES + c * 8192, Whb + c * 64, Hv);
    asm volatile("cp.async.commit_group;" ::: "memory");
    asm volatile("cp.async.wait_group 0;" ::: "memory");
    __syncthreads();

    unsigned expect = 0;
    const int gid = blockIdx.x * NTHR + tid;   // 0..65535 == Bv*Hv/2

    for (int w = 0; w <= Tv; w++) {
        const int p = w & 1;
        const bool active = (seg == 1) || (seg == 2) || (w < Tv);

        if (active) {
            const __nv_bfloat16 *Ah, *Al;
            size_t astr;
            if (seg <= 1)      { Ah = g_h0h[p] + (size_t)r0 * Hv; Al = g_h0l[p] + (size_t)r0 * Hv; astr = Hv; }
            else if (seg == 2) { Ah = g_h1h[p] + (size_t)r0 * Hv; Al = g_h1l[p] + (size_t)r0 * Hv; astr = Hv; }
            else { Ah = g_xh + ((size_t)r0 * Tv + w) * Hv; Al = g_xl + ((size_t)r0 * Tv + w) * Hv; astr = (size_t)Tv * Hv; }

            auto load_chunk = [&](int b, int c) {
                load_tile(sb + OFF_AH(b), Ah + c * 64, astr);
                load_tile(sb + OFF_AL(b), Al + c * 64, astr);
                load_tile(sb + OFF_WL(b), Wlb + c * 64, Hv);
                asm volatile("cp.async.commit_group;" ::: "memory");
            };

            float acc[8][4];
#pragma unroll
            for (int i = 0; i < 8; i++)
#pragma unroll
                for (int q = 0; q < 4; q++) acc[i][q] = 0.f;

            load_chunk(0, 0);
            load_chunk(1, 1);

#pragma unroll 1
            for (int c = 0; c < 16; c++) {
                const int b = c & 1;
                if (c < 15) asm volatile("cp.async.wait_group 1;" ::: "memory");
                else        asm volatile("cp.async.wait_group 0;" ::: "memory");
                __syncthreads();

                const uint32_t sWr = sb + OFF_WRES + c * 8192;
                uint32_t ah0[4], ah1[4], al0[4], al1[4], wh[8], wl[8];
                ldm4(ah0, sb + OFF_AH(b) + abase0 + ka);
                ldm4(ah1, sb + OFF_AH(b) + abase1 + ka);
                ldm4(al0, sb + OFF_AL(b) + abase0 + ka);
                ldm4(al1, sb + OFF_AL(b) + abase1 + ka);
                ldm4(wh,     sWr + wbase0 + kw);
                ldm4(wh + 4, sWr + wbase1 + kw);
                ldm4(wl,     sb + OFF_WL(b) + wbase0 + kw);
                ldm4(wl + 4, sb + OFF_WL(b) + wbase1 + kw);
#pragma unroll
                for (int i = 0; i < 2; i++) {
                    const uint32_t* ah = i ? ah1 : ah0;
                    const uint32_t* al = i ? al1 : al0;
#pragma unroll
                    for (int j = 0; j < 4; j++) {
                        const uint32_t* bh = &wh[(j >> 1) * 4 + (j & 1) * 2];
                        const uint32_t* bl = &wl[(j >> 1) * 4 + (j & 1) * 2];
                        float* a_ = acc[i * 4 + j];
                        mma16816(a_, ah, bh);
                        mma16816(a_, al, bh);
                        mma16816(a_, ah, bl);
                    }
                }
                __syncthreads();
                if (c + 2 < 16) load_chunk(b, c + 2);
            }

            // ---- combine 4 k-partials via smem; kq0 warps write C tile ----
            float* cmb = (float*)(smem + OFF_CMB);
            if (kq) {
                float* dst = cmb + ((kq - 1) * 4 + tw) * 1024;
#pragma unroll
                for (int r = 0; r < 32; r++)
                    dst[r * 32 + lane] = acc[r >> 2][r & 3];
            }
            __syncthreads();
            if (!kq) {
#pragma unroll
                for (int r = 0; r < 32; r++) {
                    float s = acc[r >> 2][r & 3];
#pragma unroll
                    for (int kk = 0; kk < 3; kk++)
                        s += cmb[(kk * 4 + tw) * 1024 + r * 32 + lane];
                    acc[r >> 2][r & 3] = s;
                }
                const int g = lane >> 2, tq = lane & 3;
#pragma unroll
                for (int i = 0; i < 2; i++) {
                    float* Cb = g_C + (size_t)(r0 + wr * 32 + i * 16 + g) * 4096
                              + ctc * 64 + wc * 32 + tq * 2;
#pragma unroll
                    for (int j = 0; j < 4; j++) {
                        int t = i * 4 + j;
                        float2 v0, v1;
                        v0.x = acc[t][0]; v0.y = acc[t][1];
                        v1.x = acc[t][2]; v1.y = acc[t][3];
                        *(float2*)(Cb + j * 8) = v0;
                        *(float2*)(Cb + 8 * 4096 + j * 8) = v1;
                    }
                }
            }
        }
        gbar(++expect);

        // ---------------- finalize: one float2 per thread ----------------
        {
            int bb = gid >> 9;
            int jj = (gid & 511) << 1;
            const float* Crow = g_C + (size_t)bb * 4096 + jj;

            if (w < Tv) {
                float2 c0 = __ldcg((const float2*)(Crow));
                float2 c3 = __ldcg((const float2*)(Crow + 3072));
                float2 bs = *(const float2*)&g_bsum[jj];
                float z0 = tanhf(c0.x + c3.x + bs.x);
                float z1 = tanhf(c0.y + c3.y + bs.y);
                uint32_t uh, ul;
                split2(z0, z1, uh, ul);
                *(uint32_t*)&g_h0h[p ^ 1][bb * Hv + jj] = uh;
                *(uint32_t*)&g_h0l[p ^ 1][bb * Hv + jj] = ul;
                if (w == Tv - 1 && has_hn) {
                    float2 o; o.x = z0; o.y = z1;
                    *(float2*)&out[(size_t)Bv * Tv * Hv + (size_t)bb * 2 * Hv + jj] = o;
                }
            }
            if (w >= 1) {
                float2 c1 = __ldcg((const float2*)(Crow + 1024));
                float2 c2 = __ldcg((const float2*)(Crow + 2048));
                float2 bs = *(const float2*)&g_bsum[Hv + jj];
                float z0 = tanhf(c1.x + c2.x + bs.x);
                float z1 = tanhf(c1.y + c2.y + bs.y);
                uint32_t uh, ul;
                split2(z0, z1, uh, ul);
                *(uint32_t*)&g_h1h[p ^ 1][bb * Hv + jj] = uh;
                *(uint32_t*)&g_h1l[p ^ 1][bb * Hv + jj] = ul;
                float2 o; o.x = z0; o.y = z1;
                *(float2*)&out[((size_t)bb * Tv + (w - 1)) * Hv + jj] = o;
                if (w == Tv && has_hn)
                    *(float2*)&out[(size_t)Bv * Tv * Hv + (size_t)bb * 2 * Hv + Hv + jj] = o;
            }
        }
        gbar(++expect);
    }
}

// ---------------- launcher -----------------------------------------------------------
extern "C" void kernel_launch(void* const* d_in, const int* in_sizes, int n_in,
                              void* d_out, int out_size)
{
    (void)in_sizes; (void)n_in;
    const float* x  = (const float*)d_in[0];
    const float* h0 = (const float*)d_in[1];
    const float* Wi = (const float*)d_in[2];
    const float* bi = (const float*)d_in[3];
    const float* Wh = (const float*)d_in[4];
    const float* bh = (const float*)d_in[5];
    float* out = (float*)d_out;

    cudaFuncSetAttribute(k_persist, cudaFuncAttributeMaxDynamicSharedMemorySize, SMEM_SZ);

    int has_hn = (out_size >= Bv * Tv * Hv + Bv * 2 * Hv) ? 1 : 0;

    k_init<<<512, 256>>>(h0, bi, bh);
    k_splitx<<<32768, 256>>>(x);
    k_splitw<<<dim3(32, 32, 4), dim3(32, 8)>>>(Wi, Wh);
    k_persist<<<GRID, NTHR, SMEM_SZ>>>(out, has_hn);
}